// round 8
// baseline (speedup 1.0000x reference)
#include <cuda_runtime.h>

// Problem constants (shapes are fixed by the dataset).
#define N_ATOMS_C 20000
#define CAP 96          // per-atom bucket capacity; dataset max degree ~60
#define OVF_CAP 8192
#define MP_SCALING 0.1f

// Scratch: __device__ globals (no allocations allowed; zero-initialized at
// module load). Invariant: g_count/g_ovf_count are 0 on entry to
// kernel_launch and restored to 0 by gather_kernel, so every call does
// identical work.
__device__ int  g_count[N_ATOMS_C];
__device__ int2 g_bucket[N_ATOMS_C * CAP];   // (edge_id, neighbor_id)
__device__ int  g_ovf_count;
__device__ int  g_ovf[OVF_CAP];

__device__ __forceinline__ void scatter_one(int e, int c, int n) {
    int pos = atomicAdd(&g_count[c], 1);
    if (pos < CAP) {
        g_bucket[c * CAP + pos] = make_int2(e, n);
    } else {
        int o = atomicAdd(&g_ovf_count, 1);
        if (o < OVF_CAP) g_ovf[o] = e;
    }
}

__global__ void scatter_kernel(const int* __restrict__ centers,
                               const int* __restrict__ neighbors, int E) {
    int t = blockIdx.x * blockDim.x + threadIdx.x;
    int e = t * 2;
    if (e + 1 < E) {
        int2 c = *(const int2*)(centers + e);
        int2 n = *(const int2*)(neighbors + e);
        scatter_one(e,     c.x, n.x);
        scatter_one(e + 1, c.y, n.y);
    } else if (e < E) {
        scatter_one(e, centers[e], neighbors[e]);
    }
}

// Single-edge accumulate (tail / overflow path).
__device__ __forceinline__ void edge_accum(
    float acc[16], int k,
    const float* __restrict__ sh,
    const float* __restrict__ rb,
    const float* __restrict__ emb,
    int e, int n)
{
    const float* rbe = rb + (size_t)e * 128 + k;
    float r0 = __ldg(rbe), r1 = __ldg(rbe + 32), r2 = __ldg(rbe + 64), r3 = __ldg(rbe + 96);
    float em = __ldg(emb + (size_t)n * 32 + k);
    float sv = (k < 16) ? __ldg(sh + (size_t)e * 16 + k) : 0.0f;
    float t0 = r0 * em, t1 = r1 * em, t2 = r2 * em, t3 = r3 * em;
#pragma unroll
    for (int m = 0; m < 16; m++) {
        float s = __shfl_sync(0xffffffffu, sv, m);
        float t = (m < 1) ? t0 : (m < 4) ? t1 : (m < 9) ? t2 : t3;
        acc[m] = fmaf(s, t, acc[m]);
    }
}

// One warp per atom; lane = k. 2-edge unroll (12 front-batched LDGs/group)
// keeps regs <= 51 so 40 warps/SM are resident (vs 25.6 at 64 regs): the
// MLP comes from warp count, not per-warp depth. The min-blocks clause is
// the load-bearing part.
__global__ __launch_bounds__(256, 5) void gather_kernel(
    const float* __restrict__ sh, const float* __restrict__ rb,
    const float* __restrict__ emb,
    const int* __restrict__ centers, const int* __restrict__ neighbors,
    float* __restrict__ out, int n_atoms)
{
    int a = blockIdx.x * 8 + (threadIdx.x >> 5);
    if (a >= n_atoms) return;
    int k = threadIdx.x & 31;

    int deg_raw = g_count[a];
    int deg = deg_raw > CAP ? CAP : deg_raw;

    float acc[16];
#pragma unroll
    for (int m = 0; m < 16; m++) acc[m] = 0.0f;

    const int2* bk = g_bucket + (size_t)a * CAP;

    int i = 0;
    for (; i + 2 <= deg; i += 2) {
        int4 b = __ldg((const int4*)(bk + i));   // e0,n0,e1,n1

        // ---- front-batched load phase (11 independent LDGs) ----
        const float* p0 = rb + (size_t)b.x * 128 + k;
        const float* p1 = rb + (size_t)b.z * 128 + k;
        float r00=__ldg(p0), r01=__ldg(p0+32), r02=__ldg(p0+64), r03=__ldg(p0+96);
        float r10=__ldg(p1), r11=__ldg(p1+32), r12=__ldg(p1+64), r13=__ldg(p1+96);
        float em0 = __ldg(emb + (size_t)b.y * 32 + k);
        float em1 = __ldg(emb + (size_t)b.w * 32 + k);
        // one LDG covers both sh rows: lanes 0-15 -> edge0, 16-31 -> edge1
        float sv  = __ldg(sh + ((k < 16) ? (size_t)b.x * 16 + k
                                         : (size_t)b.z * 16 + (k - 16)));

        // ---- compute phase ----
        float t00=r00*em0, t01=r01*em0, t02=r02*em0, t03=r03*em0;
        float t10=r10*em1, t11=r11*em1, t12=r12*em1, t13=r13*em1;
#pragma unroll
        for (int m = 0; m < 16; m++) {
            float s0 = __shfl_sync(0xffffffffu, sv, m);
            float s1 = __shfl_sync(0xffffffffu, sv, m + 16);
            float u0 = (m < 1) ? t00 : (m < 4) ? t01 : (m < 9) ? t02 : t03;
            float u1 = (m < 1) ? t10 : (m < 4) ? t11 : (m < 9) ? t12 : t13;
            acc[m] = fmaf(s0, u0, acc[m]);
            acc[m] = fmaf(s1, u1, acc[m]);
        }
    }
    if (i < deg) {                                // tail (<=1 edge)
        int2 en = __ldg(bk + i);
        edge_accum(acc, k, sh, rb, emb, en.x, en.y);
    }

    // Overflow edges for this atom (empty on this dataset: max deg ~60 << CAP).
    if (deg_raw > CAP) {
        int novf = g_ovf_count;
        if (novf > OVF_CAP) novf = OVF_CAP;
        for (int j = 0; j < novf; j++) {
            int e = g_ovf[j];
            if (centers[e] == a) edge_accum(acc, k, sh, rb, emb, e, neighbors[e]);
        }
    }

    float* o = out + (size_t)a * 512 + k;
#pragma unroll
    for (int m = 0; m < 16; m++) o[m * 32] = acc[m] * MP_SCALING;

    // Restore scratch invariant for the next graph replay.
    if (k == 0) g_count[a] = 0;
    if (a == 0 && k == 0) g_ovf_count = 0;
}

extern "C" void kernel_launch(void* const* d_in, const int* in_sizes, int n_in,
                              void* d_out, int out_size) {
    const float* sh        = (const float*)d_in[0];  // (E, 16)
    const float* rb        = (const float*)d_in[1];  // (E, 4, 32)
    const float* emb       = (const float*)d_in[2];  // (n_atoms, 32)
    const int*   centers   = (const int*)d_in[3];    // (E,)
    const int*   neighbors = (const int*)d_in[4];    // (E,)
    float*       out       = (float*)d_out;          // (n_atoms, 16, 32)

    int E       = in_sizes[0] / 16;
    int n_atoms = in_sizes[2] / 32;

    scatter_kernel<<<(E / 2 + 255) / 256, 256>>>(centers, neighbors, E);
    gather_kernel<<<(n_atoms + 7) / 8, 256>>>(sh, rb, emb, centers, neighbors,
                                              out, n_atoms);
}

// round 9
// speedup vs baseline: 1.1019x; 1.1019x over previous
#include <cuda_runtime.h>

// Problem constants (shapes are fixed by the dataset).
#define N_ATOMS_C 20000
#define CAP 96          // per-atom bucket capacity; dataset max degree ~60
#define OVF_CAP 8192
#define MP_SCALING 0.1f

// Scratch: __device__ globals (no allocations allowed; zero-initialized at
// module load). Invariant: g_count/g_ovf_count are 0 on entry to
// kernel_launch and restored to 0 by gather_kernel, so every call does
// identical work.
__device__ int  g_count[N_ATOMS_C];
__device__ int2 g_bucket[N_ATOMS_C * CAP];   // (edge_id, neighbor_id)
__device__ int  g_ovf_count;
__device__ int  g_ovf[OVF_CAP];

__device__ __forceinline__ void scatter_one(int e, int c, int n) {
    int pos = atomicAdd(&g_count[c], 1);
    if (pos < CAP) {
        g_bucket[c * CAP + pos] = make_int2(e, n);
    } else {
        int o = atomicAdd(&g_ovf_count, 1);
        if (o < OVF_CAP) g_ovf[o] = e;
    }
}

// 4 edges per thread: 4 independent atomic->store chains in flight.
__global__ void scatter_kernel(const int* __restrict__ centers,
                               const int* __restrict__ neighbors, int E) {
    int t = blockIdx.x * blockDim.x + threadIdx.x;
    int e = t * 4;
    if (e + 3 < E) {
        int4 c = __ldg((const int4*)(centers + e));
        int4 n = __ldg((const int4*)(neighbors + e));
        scatter_one(e,     c.x, n.x);
        scatter_one(e + 1, c.y, n.y);
        scatter_one(e + 2, c.z, n.z);
        scatter_one(e + 3, c.w, n.w);
    } else {
        for (int j = e; j < E; j++) scatter_one(j, centers[j], neighbors[j]);
    }
}

// Single-edge accumulate (tail / overflow path).
__device__ __forceinline__ void edge_accum(
    float acc[16], int k,
    const float* __restrict__ sh,
    const float* __restrict__ rb,
    const float* __restrict__ emb,
    int e, int n)
{
    const float* rbe = rb + (size_t)e * 128 + k;
    float r0 = __ldg(rbe), r1 = __ldg(rbe + 32), r2 = __ldg(rbe + 64), r3 = __ldg(rbe + 96);
    float em = __ldg(emb + (size_t)n * 32 + k);
    float sv = (k < 16) ? __ldg(sh + (size_t)e * 16 + k) : 0.0f;
    float t0 = r0 * em, t1 = r1 * em, t2 = r2 * em, t3 = r3 * em;
#pragma unroll
    for (int m = 0; m < 16; m++) {
        float s = __shfl_sync(0xffffffffu, sv, m);
        float t = (m < 1) ? t0 : (m < 4) ? t1 : (m < 9) ? t2 : t3;
        acc[m] = fmaf(s, t, acc[m]);
    }
}

// One warp per atom; lane = k. 4-edge unroll, 24 front-batched LDGs/group.
// The next group's bucket entries are prefetched during the current group's
// compute phase, so no iteration begins with a dependent L2 round trip.
__global__ __launch_bounds__(256) void gather_kernel(
    const float* __restrict__ sh, const float* __restrict__ rb,
    const float* __restrict__ emb,
    const int* __restrict__ centers, const int* __restrict__ neighbors,
    float* __restrict__ out, int n_atoms)
{
    int a = blockIdx.x * 8 + (threadIdx.x >> 5);
    if (a >= n_atoms) return;
    int k = threadIdx.x & 31;

    int deg_raw = g_count[a];
    int deg = deg_raw > CAP ? CAP : deg_raw;

    float acc[16];
#pragma unroll
    for (int m = 0; m < 16; m++) acc[m] = 0.0f;

    const int2* bk = g_bucket + (size_t)a * CAP;

    int4 bA = make_int4(0,0,0,0), bB = bA;
    if (deg >= 4) {
        bA = __ldg((const int4*)bk);          // e0,n0,e1,n1
        bB = __ldg((const int4*)(bk + 2));    // e2,n2,e3,n3
    }

    int i = 0;
    for (; i + 4 <= deg; i += 4) {
        // Prefetch next group's bucket entries (L2 hit, hidden under compute).
        int4 nA = bA, nB = bB;
        if (i + 8 <= deg) {
            nA = __ldg((const int4*)(bk + i + 4));
            nB = __ldg((const int4*)(bk + i + 6));
        }

        // ---- front-batched load phase ----
        const float* p0 = rb + (size_t)bA.x * 128 + k;
        const float* p1 = rb + (size_t)bA.z * 128 + k;
        const float* p2 = rb + (size_t)bB.x * 128 + k;
        const float* p3 = rb + (size_t)bB.z * 128 + k;
        float r00=__ldg(p0), r01=__ldg(p0+32), r02=__ldg(p0+64), r03=__ldg(p0+96);
        float r10=__ldg(p1), r11=__ldg(p1+32), r12=__ldg(p1+64), r13=__ldg(p1+96);
        float r20=__ldg(p2), r21=__ldg(p2+32), r22=__ldg(p2+64), r23=__ldg(p2+96);
        float r30=__ldg(p3), r31=__ldg(p3+32), r32=__ldg(p3+64), r33=__ldg(p3+96);
        float em0 = __ldg(emb + (size_t)bA.y * 32 + k);
        float em1 = __ldg(emb + (size_t)bA.w * 32 + k);
        float em2 = __ldg(emb + (size_t)bB.y * 32 + k);
        float em3 = __ldg(emb + (size_t)bB.w * 32 + k);
        float svA = __ldg(sh + ((k < 16) ? (size_t)bA.x * 16 + k
                                         : (size_t)bA.z * 16 + (k - 16)));
        float svB = __ldg(sh + ((k < 16) ? (size_t)bB.x * 16 + k
                                         : (size_t)bB.z * 16 + (k - 16)));

        // ---- compute phase ----
        float t00=r00*em0, t01=r01*em0, t02=r02*em0, t03=r03*em0;
        float t10=r10*em1, t11=r11*em1, t12=r12*em1, t13=r13*em1;
        float t20=r20*em2, t21=r21*em2, t22=r22*em2, t23=r23*em2;
        float t30=r30*em3, t31=r31*em3, t32=r32*em3, t33=r33*em3;
#pragma unroll
        for (int m = 0; m < 16; m++) {
            float s0 = __shfl_sync(0xffffffffu, svA, m);
            float s1 = __shfl_sync(0xffffffffu, svA, m + 16);
            float s2 = __shfl_sync(0xffffffffu, svB, m);
            float s3 = __shfl_sync(0xffffffffu, svB, m + 16);
            float u0 = (m < 1) ? t00 : (m < 4) ? t01 : (m < 9) ? t02 : t03;
            float u1 = (m < 1) ? t10 : (m < 4) ? t11 : (m < 9) ? t12 : t13;
            float u2 = (m < 1) ? t20 : (m < 4) ? t21 : (m < 9) ? t22 : t23;
            float u3 = (m < 1) ? t30 : (m < 4) ? t31 : (m < 9) ? t32 : t33;
            acc[m] = fmaf(s0, u0, acc[m]);
            acc[m] = fmaf(s1, u1, acc[m]);
            acc[m] = fmaf(s2, u2, acc[m]);
            acc[m] = fmaf(s3, u3, acc[m]);
        }
        bA = nA; bB = nB;
    }
    for (; i < deg; i++) {                       // tail (<=3 edges)
        int2 en = __ldg(bk + i);
        edge_accum(acc, k, sh, rb, emb, en.x, en.y);
    }

    // Overflow edges for this atom (empty on this dataset: max deg ~60 << CAP).
    if (deg_raw > CAP) {
        int novf = g_ovf_count;
        if (novf > OVF_CAP) novf = OVF_CAP;
        for (int j = 0; j < novf; j++) {
            int e = g_ovf[j];
            if (centers[e] == a) edge_accum(acc, k, sh, rb, emb, e, neighbors[e]);
        }
    }

    float* o = out + (size_t)a * 512 + k;
#pragma unroll
    for (int m = 0; m < 16; m++) o[m * 32] = acc[m] * MP_SCALING;

    // Restore scratch invariant for the next graph replay.
    if (k == 0) g_count[a] = 0;
    if (a == 0 && k == 0) g_ovf_count = 0;
}

extern "C" void kernel_launch(void* const* d_in, const int* in_sizes, int n_in,
                              void* d_out, int out_size) {
    const float* sh        = (const float*)d_in[0];  // (E, 16)
    const float* rb        = (const float*)d_in[1];  // (E, 4, 32)
    const float* emb       = (const float*)d_in[2];  // (n_atoms, 32)
    const int*   centers   = (const int*)d_in[3];    // (E,)
    const int*   neighbors = (const int*)d_in[4];    // (E,)
    float*       out       = (float*)d_out;          // (n_atoms, 16, 32)

    int E       = in_sizes[0] / 16;
    int n_atoms = in_sizes[2] / 32;

    scatter_kernel<<<(E / 4 + 255) / 256, 256>>>(centers, neighbors, E);
    gather_kernel<<<(n_atoms + 7) / 8, 256>>>(sh, rb, emb, centers, neighbors,
                                              out, n_atoms);
}

// round 10
// speedup vs baseline: 1.1730x; 1.0645x over previous
#include <cuda_runtime.h>

// Problem constants (shapes are fixed by the dataset).
#define N_ATOMS_C 20000
#define CAP 96          // per-atom bucket capacity; dataset max degree ~60
#define OVF_CAP 8192
#define MP_SCALING 0.1f

// Scratch: __device__ globals (no allocations allowed; zero-initialized at
// module load). Invariant: g_count/g_ovf_count are 0 on entry to
// kernel_launch and restored to 0 by gather_kernel, so every call does
// identical work.
__device__ int  g_count[N_ATOMS_C];
__device__ int2 g_bucket[N_ATOMS_C * CAP];   // (edge_id, neighbor_id)
__device__ int  g_ovf_count;
__device__ int  g_ovf[OVF_CAP];

__device__ __forceinline__ void scatter_one(int e, int c, int n) {
    int pos = atomicAdd(&g_count[c], 1);
    if (pos < CAP) {
        g_bucket[c * CAP + pos] = make_int2(e, n);
    } else {
        int o = atomicAdd(&g_ovf_count, 1);
        if (o < OVF_CAP) g_ovf[o] = e;
    }
}

// 4 edges per thread: 4 independent atomic->store chains in flight.
__global__ void scatter_kernel(const int* __restrict__ centers,
                               const int* __restrict__ neighbors, int E) {
    int t = blockIdx.x * blockDim.x + threadIdx.x;
    int e = t * 4;
    if (e + 3 < E) {
        int4 c = __ldg((const int4*)(centers + e));
        int4 n = __ldg((const int4*)(neighbors + e));
        scatter_one(e,     c.x, n.x);
        scatter_one(e + 1, c.y, n.y);
        scatter_one(e + 2, c.z, n.z);
        scatter_one(e + 3, c.w, n.w);
    } else {
        for (int j = e; j < E; j++) scatter_one(j, centers[j], neighbors[j]);
    }
}

// Single-edge accumulate (tail / overflow path).
__device__ __forceinline__ void edge_accum(
    float acc[16], int k,
    const float* __restrict__ sh,
    const float* __restrict__ rb,
    const float* __restrict__ emb,
    int e, int n)
{
    const float* rbe = rb + (size_t)e * 128 + k;
    float r0 = __ldcs(rbe), r1 = __ldcs(rbe + 32), r2 = __ldcs(rbe + 64), r3 = __ldcs(rbe + 96);
    float em = __ldg(emb + (size_t)n * 32 + k);
    float sv = (k < 16) ? __ldg(sh + (size_t)e * 16 + k) : 0.0f;
    float t0 = r0 * em, t1 = r1 * em, t2 = r2 * em, t3 = r3 * em;
#pragma unroll
    for (int m = 0; m < 16; m++) {
        float s = __shfl_sync(0xffffffffu, sv, m);
        float t = (m < 1) ? t0 : (m < 4) ? t1 : (m < 9) ? t2 : t3;
        acc[m] = fmaf(s, t, acc[m]);
    }
}

// One warp per atom; lane = k. 4-edge unroll, 24 front-batched LDGs/group,
// next group's bucket entries prefetched during compute. rb is loaded with
// evict-first policy (read-exactly-once, 327MB) so it doesn't flush the
// reusable L2 residents (emb, bucket, indices); out is stored streaming.
__global__ __launch_bounds__(256) void gather_kernel(
    const float* __restrict__ sh, const float* __restrict__ rb,
    const float* __restrict__ emb,
    const int* __restrict__ centers, const int* __restrict__ neighbors,
    float* __restrict__ out, int n_atoms)
{
    int a = blockIdx.x * 8 + (threadIdx.x >> 5);
    if (a >= n_atoms) return;
    int k = threadIdx.x & 31;

    int deg_raw = g_count[a];
    int deg = deg_raw > CAP ? CAP : deg_raw;

    float acc[16];
#pragma unroll
    for (int m = 0; m < 16; m++) acc[m] = 0.0f;

    const int2* bk = g_bucket + (size_t)a * CAP;

    int4 bA = make_int4(0,0,0,0), bB = bA;
    if (deg >= 4) {
        bA = __ldg((const int4*)bk);          // e0,n0,e1,n1
        bB = __ldg((const int4*)(bk + 2));    // e2,n2,e3,n3
    }

    int i = 0;
    for (; i + 4 <= deg; i += 4) {
        // Prefetch next group's bucket entries (L2 hit, hidden under compute).
        int4 nA = bA, nB = bB;
        if (i + 8 <= deg) {
            nA = __ldg((const int4*)(bk + i + 4));
            nB = __ldg((const int4*)(bk + i + 6));
        }

        // ---- front-batched load phase ----
        const float* p0 = rb + (size_t)bA.x * 128 + k;
        const float* p1 = rb + (size_t)bA.z * 128 + k;
        const float* p2 = rb + (size_t)bB.x * 128 + k;
        const float* p3 = rb + (size_t)bB.z * 128 + k;
        float r00=__ldcs(p0), r01=__ldcs(p0+32), r02=__ldcs(p0+64), r03=__ldcs(p0+96);
        float r10=__ldcs(p1), r11=__ldcs(p1+32), r12=__ldcs(p1+64), r13=__ldcs(p1+96);
        float r20=__ldcs(p2), r21=__ldcs(p2+32), r22=__ldcs(p2+64), r23=__ldcs(p2+96);
        float r30=__ldcs(p3), r31=__ldcs(p3+32), r32=__ldcs(p3+64), r33=__ldcs(p3+96);
        float em0 = __ldg(emb + (size_t)bA.y * 32 + k);
        float em1 = __ldg(emb + (size_t)bA.w * 32 + k);
        float em2 = __ldg(emb + (size_t)bB.y * 32 + k);
        float em3 = __ldg(emb + (size_t)bB.w * 32 + k);
        float svA = __ldg(sh + ((k < 16) ? (size_t)bA.x * 16 + k
                                         : (size_t)bA.z * 16 + (k - 16)));
        float svB = __ldg(sh + ((k < 16) ? (size_t)bB.x * 16 + k
                                         : (size_t)bB.z * 16 + (k - 16)));

        // ---- compute phase ----
        float t00=r00*em0, t01=r01*em0, t02=r02*em0, t03=r03*em0;
        float t10=r10*em1, t11=r11*em1, t12=r12*em1, t13=r13*em1;
        float t20=r20*em2, t21=r21*em2, t22=r22*em2, t23=r23*em2;
        float t30=r30*em3, t31=r31*em3, t32=r32*em3, t33=r33*em3;
#pragma unroll
        for (int m = 0; m < 16; m++) {
            float s0 = __shfl_sync(0xffffffffu, svA, m);
            float s1 = __shfl_sync(0xffffffffu, svA, m + 16);
            float s2 = __shfl_sync(0xffffffffu, svB, m);
            float s3 = __shfl_sync(0xffffffffu, svB, m + 16);
            float u0 = (m < 1) ? t00 : (m < 4) ? t01 : (m < 9) ? t02 : t03;
            float u1 = (m < 1) ? t10 : (m < 4) ? t11 : (m < 9) ? t12 : t13;
            float u2 = (m < 1) ? t20 : (m < 4) ? t21 : (m < 9) ? t22 : t23;
            float u3 = (m < 1) ? t30 : (m < 4) ? t31 : (m < 9) ? t32 : t33;
            acc[m] = fmaf(s0, u0, acc[m]);
            acc[m] = fmaf(s1, u1, acc[m]);
            acc[m] = fmaf(s2, u2, acc[m]);
            acc[m] = fmaf(s3, u3, acc[m]);
        }
        bA = nA; bB = nB;
    }
    for (; i < deg; i++) {                       // tail (<=3 edges)
        int2 en = __ldg(bk + i);
        edge_accum(acc, k, sh, rb, emb, en.x, en.y);
    }

    // Overflow edges for this atom (empty on this dataset: max deg ~60 << CAP).
    if (deg_raw > CAP) {
        int novf = g_ovf_count;
        if (novf > OVF_CAP) novf = OVF_CAP;
        for (int j = 0; j < novf; j++) {
            int e = g_ovf[j];
            if (centers[e] == a) edge_accum(acc, k, sh, rb, emb, e, neighbors[e]);
        }
    }

    // Streaming stores: out is write-once, never re-read.
    float* o = out + (size_t)a * 512 + k;
#pragma unroll
    for (int m = 0; m < 16; m++) __stcs(o + m * 32, acc[m] * MP_SCALING);

    // Restore scratch invariant for the next graph replay.
    if (k == 0) g_count[a] = 0;
    if (a == 0 && k == 0) g_ovf_count = 0;
}

extern "C" void kernel_launch(void* const* d_in, const int* in_sizes, int n_in,
                              void* d_out, int out_size) {
    const float* sh        = (const float*)d_in[0];  // (E, 16)
    const float* rb        = (const float*)d_in[1];  // (E, 4, 32)
    const float* emb       = (const float*)d_in[2];  // (n_atoms, 32)
    const int*   centers   = (const int*)d_in[3];    // (E,)
    const int*   neighbors = (const int*)d_in[4];    // (E,)
    float*       out       = (float*)d_out;          // (n_atoms, 16, 32)

    int E       = in_sizes[0] / 16;
    int n_atoms = in_sizes[2] / 32;

    scatter_kernel<<<(E / 4 + 511) / 512, 512>>>(centers, neighbors, E);
    gather_kernel<<<(n_atoms + 7) / 8, 256>>>(sh, rb, emb, centers, neighbors,
                                              out, n_atoms);
}